// round 14
// baseline (speedup 1.0000x reference)
#include <cuda_runtime.h>
#include <cstdint>

#define BB 32
#define SS 2048
#define DD 64

// ===================== tf32 split + mma.sync helpers ========================
__device__ __forceinline__ void split_tf32(float x, float& hi, float& lo) {
    uint32_t h;
    asm("cvt.rna.tf32.f32 %0, %1;" : "=r"(h) : "f"(x));
    hi = __uint_as_float(h);
    float rem = x - hi;
    uint32_t l;
    asm("cvt.rna.tf32.f32 %0, %1;" : "=r"(l) : "f"(rem));
    lo = __uint_as_float(l);
}
__device__ __forceinline__ void split4(float4 v, float4& h, float4& l) {
    split_tf32(v.x, h.x, l.x); split_tf32(v.y, h.y, l.y);
    split_tf32(v.z, h.z, l.z); split_tf32(v.w, h.w, l.w);
}
__device__ __forceinline__ void split2(float2 v, float2& h, float2& l) {
    split_tf32(v.x, h.x, l.x); split_tf32(v.y, h.y, l.y);
}

// D += A(16x8 tf32) * B(8x8 tf32), m16n8k8
__device__ __forceinline__ void mma8(float* c, float4 a, float2 b) {
    asm volatile(
        "mma.sync.aligned.m16n8k8.row.col.f32.tf32.tf32.f32 "
        "{%0,%1,%2,%3}, {%4,%5,%6,%7}, {%8,%9}, {%0,%1,%2,%3};"
        : "+f"(c[0]), "+f"(c[1]), "+f"(c[2]), "+f"(c[3])
        : "r"(__float_as_uint(a.x)), "r"(__float_as_uint(a.y)),
          "r"(__float_as_uint(a.z)), "r"(__float_as_uint(a.w)),
          "r"(__float_as_uint(b.x)), "r"(__float_as_uint(b.y)));
}

// Fragment-permuted smem float indices (validated, rel_err 5e-6).
__device__ __forceinline__ int a_idx(int row, int col, int KS) {
    int mt = row >> 4, r = row & 15, ks = col >> 3, cc = col & 7;
    int lane = ((r & 7) << 2) | (cc & 3);
    int reg = (r >> 3) | ((cc >> 2) << 1);
    return ((((mt * KS + ks) << 5) + lane) << 2) + reg;
}
__device__ __forceinline__ int b_idx(int kk, int n, int KS) {
    int nt = n >> 3, g = n & 7, ks = kk >> 3, c = kk & 7;
    int lane = (g << 2) | (c & 3);
    int reg = c >> 2;
    return ((((nt * KS + ks) << 5) + lane) << 1) + reg;
}

// ===================== K1: scores = (Q*0.125) @ K^T (unchanged, 186us) ======
#define QK_SMEM 67584

__global__ __launch_bounds__(256, 2) void qk_mma(const float* __restrict__ Q,
                                                 const float* __restrict__ Km,
                                                 const int* __restrict__ vlen,
                                                 float* __restrict__ W) {
    const int kt = blockIdx.x, qt = blockIdx.y, b = blockIdx.z;
    const int L = vlen[b];
    if (L == 0 || kt * 128 >= L) return;

    extern __shared__ char S[];
    float* Af = (float*)S;
    float* Bf = (float*)(S + 32768);

    const int t = threadIdx.x;
    const float* Qb = Q + ((size_t)(b * SS + qt * 128)) * DD;
    const float* Kb = Km + ((size_t)(b * SS + kt * 128)) * DD;

#pragma unroll
    for (int i = 0; i < 8; i++) {
        int idx = t + i * 256;
        int row = idx >> 4, c0 = (idx & 15) << 2;
        float4 qv = *(const float4*)&Qb[row * DD + c0];
        float4 kv = *(const float4*)&Kb[row * DD + c0];
        Af[a_idx(row, c0 + 0, 8)] = qv.x * 0.125f;
        Af[a_idx(row, c0 + 1, 8)] = qv.y * 0.125f;
        Af[a_idx(row, c0 + 2, 8)] = qv.z * 0.125f;
        Af[a_idx(row, c0 + 3, 8)] = qv.w * 0.125f;
        Bf[b_idx(c0 + 0, row, 8)] = kv.x;
        Bf[b_idx(c0 + 1, row, 8)] = kv.y;
        Bf[b_idx(c0 + 2, row, 8)] = kv.z;
        Bf[b_idx(c0 + 3, row, 8)] = kv.w;
    }
    __syncthreads();

    const int wid = t >> 5, lane = t & 31;
    const int wm = wid >> 2, wn = wid & 3;

    float acc[4][4][4];
#pragma unroll
    for (int mt = 0; mt < 4; mt++)
#pragma unroll
        for (int nt = 0; nt < 4; nt++)
#pragma unroll
            for (int r = 0; r < 4; r++) acc[mt][nt][r] = 0.0f;

    const float4* Af4 = (const float4*)Af;
    const float2* Bf2 = (const float2*)Bf;

#pragma unroll
    for (int s = 0; s < 8; s++) {
        float2 bh[4], bl[4];
#pragma unroll
        for (int nt = 0; nt < 4; nt++) {
            float2 bv = Bf2[(((wn * 4 + nt) * 8 + s) << 5) + lane];
            split2(bv, bh[nt], bl[nt]);
        }
#pragma unroll
        for (int mt = 0; mt < 4; mt++) {
            float4 av = Af4[(((wm * 4 + mt) * 8 + s) << 5) + lane];
            float4 ah, al;
            split4(av, ah, al);
#pragma unroll
            for (int nt = 0; nt < 4; nt++) {
                mma8(acc[mt][nt], ah, bh[nt]);
                mma8(acc[mt][nt], al, bh[nt]);
                mma8(acc[mt][nt], ah, bl[nt]);
            }
        }
    }
    __syncthreads();

    float* Es = (float*)S;
    const int g = lane >> 2, cp = (lane & 3) << 1;
#pragma unroll
    for (int mt = 0; mt < 4; mt++) {
        int row0 = wm * 64 + mt * 16 + g;
#pragma unroll
        for (int nt = 0; nt < 4; nt++) {
            int col0 = wn * 32 + nt * 8 + cp;
            *(float2*)&Es[row0 * 132 + col0] = make_float2(acc[mt][nt][0], acc[mt][nt][1]);
            *(float2*)&Es[(row0 + 8) * 132 + col0] = make_float2(acc[mt][nt][2], acc[mt][nt][3]);
        }
    }
    __syncthreads();

    float* Wp = W + ((size_t)(b * SS + qt * 128)) * SS + (size_t)kt * 128;
    const int c4 = t & 31;
    for (int rr = t >> 5; rr < 128; rr += 8)
        *(float4*)&Wp[(size_t)rr * SS + c4 * 4] = *(float4*)&Es[rr * 132 + c4 * 4];
}

// ===================== K2: fused softmax + O = W @ V ========================
// CTA owns 64 q-rows of batch b. Two passes over its score strip:
//  pass 1: stream scores, exp, row-sums -> inv (smem rsum[64])
//  pass 2: per 128-k tile: re-read scores, w = exp(s)*inv (masked->0),
//          write normalized W in-place (coalesced float4), stage w into
//          A-frag layout, V into B-frag layout, split-tf32 MMA accumulate O.
//  tail cols [nkt*128, 2048) zero-filled; L==0 -> w = 1/2048 uniform
//  through the same MMA path (O = mean(V), W uniform; matches reference).
#define PV_SMEM 66048  // Af 32K + Bf 32K + rsum 256B (padded)

__global__ __launch_bounds__(256, 3) void pv_fused(float* __restrict__ W,
                                                   const float* __restrict__ V,
                                                   const int* __restrict__ vlen,
                                                   float* __restrict__ O) {
    const int qt = blockIdx.x, b = blockIdx.y;
    const int L = vlen[b];
    const bool uniform = (L == 0);
    const int nkt = uniform ? 16 : ((L + 127) >> 7);
    const int kend = nkt * 128;

    extern __shared__ char S[];
    float* Af = (float*)S;               // 64x128 w-tile, a_idx KS=16
    float* Bf = (float*)(S + 32768);     // 128x64 V-tile, b_idx KS=16
    float* rsum = (float*)(S + 65536);   // 64 row inverse sums

    const int t = threadIdx.x, wid = t >> 5, lane = t & 31;
    const int wm = wid >> 1, wn = wid & 1;  // warp: 16q x 32d

    float* Wb = W + ((size_t)(b * SS + qt * 64)) * SS;
    const float* Vb = V + (size_t)b * SS * DD;

    // ---- Pass 1: row sums of exp over valid cols ----
    if (!uniform) {
        const int r0 = t >> 3, sub = t & 7;   // 8 threads per row, rows r0, r0+32
        float sum0 = 0.0f, sum1 = 0.0f;
        const float* S0 = Wb + (size_t)r0 * SS;
        const float* S1 = Wb + (size_t)(r0 + 32) * SS;
        for (int c = sub * 4; c < kend; c += 32) {
            float4 s0 = *(const float4*)&S0[c];
            float4 s1 = *(const float4*)&S1[c];
#pragma unroll
            for (int j = 0; j < 4; j++) {
                float v0 = (&s0.x)[j], v1 = (&s1.x)[j];
                if (c + j < L) { sum0 += __expf(v0); sum1 += __expf(v1); }
            }
        }
#pragma unroll
        for (int o = 4; o; o >>= 1) {
            sum0 += __shfl_xor_sync(0xffffffffu, sum0, o);
            sum1 += __shfl_xor_sync(0xffffffffu, sum1, o);
        }
        if (sub == 0) { rsum[r0] = sum0; rsum[r0 + 32] = sum1; }
        __syncthreads();
        if (t < 64) rsum[t] = 1.0f / rsum[t];
    }

    // ---- Pass 2: normalize + write W + accumulate O ----
    float acc[4][4];
#pragma unroll
    for (int nt = 0; nt < 4; nt++)
#pragma unroll
        for (int r = 0; r < 4; r++) acc[nt][r] = 0.0f;

    const float4* Af4 = (const float4*)Af;
    const float2* Bf2 = (const float2*)Bf;
    const float U = 1.0f / 2048.0f;

    for (int kt = 0; kt < nkt; kt++) {
        __syncthreads();
        // Stage A: 64x128 score tile -> w; write W in-place; scatter to Af
#pragma unroll
        for (int i = 0; i < 8; i++) {
            int idx = t + i * 256;
            int row = idx >> 5, c0 = (idx & 31) << 2;
            float* Wp = &Wb[(size_t)row * SS + kt * 128 + c0];
            float4 sv = *(const float4*)Wp;
            float inv = uniform ? 0.0f : rsum[row];
            float w[4];
#pragma unroll
            for (int j = 0; j < 4; j++) {
                int col = kt * 128 + c0 + j;
                float s = (&sv.x)[j];
                w[j] = uniform ? U : ((col < L) ? __expf(s) * inv : 0.0f);
            }
            *(float4*)Wp = make_float4(w[0], w[1], w[2], w[3]);
            Af[a_idx(row, c0 + 0, 16)] = w[0];
            Af[a_idx(row, c0 + 1, 16)] = w[1];
            Af[a_idx(row, c0 + 2, 16)] = w[2];
            Af[a_idx(row, c0 + 3, 16)] = w[3];
        }
        // Stage B: V tile 128kv x 64d
#pragma unroll
        for (int i = 0; i < 8; i++) {
            int idx = t + i * 256;
            int kv = idx >> 4, d0 = (idx & 15) << 2;
            float4 vv = *(const float4*)&Vb[(size_t)(kt * 128 + kv) * DD + d0];
            Bf[b_idx(kv, d0 + 0, 16)] = vv.x;
            Bf[b_idx(kv, d0 + 1, 16)] = vv.y;
            Bf[b_idx(kv, d0 + 2, 16)] = vv.z;
            Bf[b_idx(kv, d0 + 3, 16)] = vv.w;
        }
        __syncthreads();

#pragma unroll 4
        for (int s = 0; s < 16; s++) {
            float4 av = Af4[((wm * 16 + s) << 5) + lane];
            float4 ah, al;
            split4(av, ah, al);
#pragma unroll
            for (int nt = 0; nt < 4; nt++) {
                float2 bv = Bf2[(((wn * 4 + nt) * 16 + s) << 5) + lane];
                float2 bh, bl;
                split2(bv, bh, bl);
                mma8(acc[nt], ah, bh);
                mma8(acc[nt], al, bh);
                mma8(acc[nt], ah, bl);
            }
        }
    }

    // ---- Tail: zero-fill masked cols [kend, 2048) ----
    if (kend < SS) {
        const float4 z4 = make_float4(0.f, 0.f, 0.f, 0.f);
        const int c40 = (kend >> 2) + lane;
        for (int r = wid; r < 64; r += 8) {
            float4* Wr = (float4*)(Wb + (size_t)r * SS);
            for (int c4 = c40; c4 < SS / 4; c4 += 32) Wr[c4] = z4;
        }
    }

    // ---- Epilogue: O (already normalized) ----
    const int g = lane >> 2, cp = (lane & 3) << 1;
    int row = qt * 64 + wm * 16 + g;
    float* Op0 = O + ((size_t)(b * SS + row)) * DD;
    float* Op1 = O + ((size_t)(b * SS + row + 8)) * DD;
#pragma unroll
    for (int nt = 0; nt < 4; nt++) {
        int col = wn * 32 + nt * 8 + cp;
        *(float2*)&Op0[col] = make_float2(acc[nt][0], acc[nt][1]);
        *(float2*)&Op1[col] = make_float2(acc[nt][2], acc[nt][3]);
    }
}

// ============================================================================
extern "C" void kernel_launch(void* const* d_in, const int* in_sizes, int n_in,
                              void* d_out, int out_size) {
    const float* Q = (const float*)d_in[0];
    const float* K = (const float*)d_in[1];
    const float* V = (const float*)d_in[2];
    const int* vlen = (const int*)d_in[3];

    const long long BSD = (long long)BB * SS * DD;
    const long long BSS = (long long)BB * SS * SS;

    float* out_o = nullptr;
    float* out_w;
    if ((long long)out_size >= BSD + BSS) {
        out_o = (float*)d_out;
        out_w = (float*)d_out + BSD;
    } else {
        out_w = (float*)d_out;
    }

    cudaFuncSetAttribute(qk_mma, cudaFuncAttributeMaxDynamicSharedMemorySize, QK_SMEM);
    cudaFuncSetAttribute(pv_fused, cudaFuncAttributeMaxDynamicSharedMemorySize, PV_SMEM);

    dim3 g1(SS / 128, SS / 128, BB);
    qk_mma<<<g1, 256, QK_SMEM>>>(Q, K, vlen, out_w);

    if (out_o) {
        dim3 g2(SS / 64, BB);
        pv_fused<<<g2, 256, PV_SMEM>>>(out_w, V, vlen, out_o);
    }
}

// round 16
// speedup vs baseline: 1.0796x; 1.0796x over previous
#include <cuda_runtime.h>
#include <cstdint>

#define BB 32
#define SS 2048
#define DD 64

__device__ float g_rowsum[BB * SS];  // per-(b,q-row) sum of exp over valid k

// ===================== tf32 split + mma.sync helpers ========================
__device__ __forceinline__ void split_tf32(float x, float& hi, float& lo) {
    uint32_t h;
    asm("cvt.rna.tf32.f32 %0, %1;" : "=r"(h) : "f"(x));
    hi = __uint_as_float(h);
    float rem = x - hi;
    uint32_t l;
    asm("cvt.rna.tf32.f32 %0, %1;" : "=r"(l) : "f"(rem));
    lo = __uint_as_float(l);
}
__device__ __forceinline__ void split4(float4 v, float4& h, float4& l) {
    split_tf32(v.x, h.x, l.x); split_tf32(v.y, h.y, l.y);
    split_tf32(v.z, h.z, l.z); split_tf32(v.w, h.w, l.w);
}
__device__ __forceinline__ void split2(float2 v, float2& h, float2& l) {
    split_tf32(v.x, h.x, l.x); split_tf32(v.y, h.y, l.y);
}

__device__ __forceinline__ void mma8(float* c, float4 a, float2 b) {
    asm volatile(
        "mma.sync.aligned.m16n8k8.row.col.f32.tf32.tf32.f32 "
        "{%0,%1,%2,%3}, {%4,%5,%6,%7}, {%8,%9}, {%0,%1,%2,%3};"
        : "+f"(c[0]), "+f"(c[1]), "+f"(c[2]), "+f"(c[3])
        : "r"(__float_as_uint(a.x)), "r"(__float_as_uint(a.y)),
          "r"(__float_as_uint(a.z)), "r"(__float_as_uint(a.w)),
          "r"(__float_as_uint(b.x)), "r"(__float_as_uint(b.y)));
}

__device__ __forceinline__ int a_idx(int row, int col, int KS) {
    int mt = row >> 4, r = row & 15, ks = col >> 3, cc = col & 7;
    int lane = ((r & 7) << 2) | (cc & 3);
    int reg = (r >> 3) | ((cc >> 2) << 1);
    return ((((mt * KS + ks) << 5) + lane) << 2) + reg;
}
__device__ __forceinline__ int b_idx(int kk, int n, int KS) {
    int nt = n >> 3, g = n & 7, ks = kk >> 3, c = kk & 7;
    int lane = (g << 2) | (c & 3);
    int reg = c >> 2;
    return ((((nt * KS + ks) << 5) + lane) << 1) + reg;
}

// ===================== K0: zero the rowsum scratch ==========================
__global__ void zero_rowsum() {
    int i = (blockIdx.x * 256 + threadIdx.x) * 4;
    *(float4*)&g_rowsum[i] = make_float4(0.f, 0.f, 0.f, 0.f);
}

// ===================== K1: E = exp((Q*0.125) @ K^T), + row sums =============
// Same validated MMA core as R9 (186us). Epilogue now: mask cols >= L,
// exp in-registers, warp-reduce partial row sums -> atomicAdd g_rowsum,
// stage E through smem, coalesced store.
#define QK_SMEM 67584

__global__ __launch_bounds__(256, 2) void qk_mma(const float* __restrict__ Q,
                                                 const float* __restrict__ Km,
                                                 const int* __restrict__ vlen,
                                                 float* __restrict__ W) {
    const int kt = blockIdx.x, qt = blockIdx.y, b = blockIdx.z;
    const int L = vlen[b];
    if (L == 0 || kt * 128 >= L) return;

    extern __shared__ char S[];
    float* Af = (float*)S;
    float* Bf = (float*)(S + 32768);

    const int t = threadIdx.x;
    const float* Qb = Q + ((size_t)(b * SS + qt * 128)) * DD;
    const float* Kb = Km + ((size_t)(b * SS + kt * 128)) * DD;

#pragma unroll
    for (int i = 0; i < 8; i++) {
        int idx = t + i * 256;
        int row = idx >> 4, c0 = (idx & 15) << 2;
        float4 qv = *(const float4*)&Qb[row * DD + c0];
        float4 kv = *(const float4*)&Kb[row * DD + c0];
        Af[a_idx(row, c0 + 0, 8)] = qv.x * 0.125f;
        Af[a_idx(row, c0 + 1, 8)] = qv.y * 0.125f;
        Af[a_idx(row, c0 + 2, 8)] = qv.z * 0.125f;
        Af[a_idx(row, c0 + 3, 8)] = qv.w * 0.125f;
        Bf[b_idx(c0 + 0, row, 8)] = kv.x;
        Bf[b_idx(c0 + 1, row, 8)] = kv.y;
        Bf[b_idx(c0 + 2, row, 8)] = kv.z;
        Bf[b_idx(c0 + 3, row, 8)] = kv.w;
    }
    __syncthreads();

    const int wid = t >> 5, lane = t & 31;
    const int wm = wid >> 2, wn = wid & 3;

    float acc[4][4][4];
#pragma unroll
    for (int mt = 0; mt < 4; mt++)
#pragma unroll
        for (int nt = 0; nt < 4; nt++)
#pragma unroll
            for (int r = 0; r < 4; r++) acc[mt][nt][r] = 0.0f;

    const float4* Af4 = (const float4*)Af;
    const float2* Bf2 = (const float2*)Bf;

#pragma unroll
    for (int s = 0; s < 8; s++) {
        float2 bh[4], bl[4];
#pragma unroll
        for (int nt = 0; nt < 4; nt++) {
            float2 bv = Bf2[(((wn * 4 + nt) * 8 + s) << 5) + lane];
            split2(bv, bh[nt], bl[nt]);
        }
#pragma unroll
        for (int mt = 0; mt < 4; mt++) {
            float4 av = Af4[(((wm * 4 + mt) * 8 + s) << 5) + lane];
            float4 ah, al;
            split4(av, ah, al);
#pragma unroll
            for (int nt = 0; nt < 4; nt++) {
                mma8(acc[mt][nt], ah, bh[nt]);
                mma8(acc[mt][nt], al, bh[nt]);
                mma8(acc[mt][nt], ah, bl[nt]);
            }
        }
    }

    // ---- exp + mask + row-sum atomics (acc becomes E) ----
    const int g = lane >> 2, cp = (lane & 3) << 1;
    const int colbase = kt * 128 + wn * 32;
    float* rs = g_rowsum + (size_t)b * SS + qt * 128 + wm * 64;
#pragma unroll
    for (int mt = 0; mt < 4; mt++) {
        float s0 = 0.f, s1 = 0.f;
#pragma unroll
        for (int nt = 0; nt < 4; nt++) {
            int cg = colbase + nt * 8 + cp;
            float e0 = (cg < L) ? __expf(acc[mt][nt][0]) : 0.f;
            float e1 = (cg + 1 < L) ? __expf(acc[mt][nt][1]) : 0.f;
            float e2 = (cg < L) ? __expf(acc[mt][nt][2]) : 0.f;
            float e3 = (cg + 1 < L) ? __expf(acc[mt][nt][3]) : 0.f;
            acc[mt][nt][0] = e0; acc[mt][nt][1] = e1;
            acc[mt][nt][2] = e2; acc[mt][nt][3] = e3;
            s0 += e0 + e1; s1 += e2 + e3;
        }
        s0 += __shfl_xor_sync(0xffffffffu, s0, 1);
        s0 += __shfl_xor_sync(0xffffffffu, s0, 2);
        s1 += __shfl_xor_sync(0xffffffffu, s1, 1);
        s1 += __shfl_xor_sync(0xffffffffu, s1, 2);
        if ((lane & 3) == 0) {
            atomicAdd(&rs[mt * 16 + g], s0);
            atomicAdd(&rs[mt * 16 + g + 8], s1);
        }
    }
    __syncthreads();

    // ---- stage E -> coalesced store ----
    float* Es = (float*)S;
#pragma unroll
    for (int mt = 0; mt < 4; mt++) {
        int row0 = wm * 64 + mt * 16 + g;
#pragma unroll
        for (int nt = 0; nt < 4; nt++) {
            int col0 = wn * 32 + nt * 8 + cp;
            *(float2*)&Es[row0 * 132 + col0] = make_float2(acc[mt][nt][0], acc[mt][nt][1]);
            *(float2*)&Es[(row0 + 8) * 132 + col0] = make_float2(acc[mt][nt][2], acc[mt][nt][3]);
        }
    }
    __syncthreads();

    float* Wp = W + ((size_t)(b * SS + qt * 128)) * SS + (size_t)kt * 128;
    const int c4 = t & 31;
    for (int rr = t >> 5; rr < 128; rr += 8)
        *(float4*)&Wp[(size_t)rr * SS + c4 * 4] = *(float4*)&Es[rr * 132 + c4 * 4];
}

// ===================== K2: single-pass normalize + O = W @ V ================
// CTA owns 64 q-rows. Per 128-k tile: (transform E->w, STG W, stage frags),
// prefetch next E tile into registers, MMA. E prefetch overlaps MMA.
#define PV_SMEM 66048

__global__ __launch_bounds__(256, 2) void pv2(float* __restrict__ W,
                                              const float* __restrict__ V,
                                              const int* __restrict__ vlen,
                                              float* __restrict__ O) {
    const int qt = blockIdx.x, b = blockIdx.y;
    const int L = vlen[b];
    const bool uniform = (L == 0);
    const int nkt = uniform ? 16 : ((L + 127) >> 7);
    const int kend = nkt * 128;

    extern __shared__ char S[];
    float* Af = (float*)S;               // 64x128 w-frag (a_idx KS=16)
    float* Bf = (float*)(S + 32768);     // 128x64 V-frag (b_idx KS=16)
    float* rsum = (float*)(S + 65536);   // 64 inverse row sums

    const int t = threadIdx.x, wid = t >> 5, lane = t & 31;
    const int wm = wid >> 1, wn = wid & 1;

    float* Wb = W + ((size_t)(b * SS + qt * 64)) * SS;
    const float* Vb = V + (size_t)b * SS * DD;

    if (t < 64) {
        float s = uniform ? 1.0f : g_rowsum[(size_t)b * SS + qt * 64 + t];
        rsum[t] = 1.0f / s;
    }
    __syncthreads();

    float acc[4][4];
#pragma unroll
    for (int nt = 0; nt < 4; nt++)
#pragma unroll
        for (int r = 0; r < 4; r++) acc[nt][r] = 0.0f;

    const float4* Af4 = (const float4*)Af;
    const float2* Bf2 = (const float2*)Bf;
    const float U = 1.0f / 2048.0f;

    const int erow = t >> 5, ec0 = (t & 31) << 2;  // this thread's E slice
    float4 e[8];
    if (!uniform) {
#pragma unroll
        for (int i = 0; i < 8; i++)
            e[i] = *(const float4*)&Wb[(size_t)(erow + i * 8) * SS + ec0];
    }

    for (int kt = 0; kt < nkt; kt++) {
        __syncthreads();  // prev MMA reads done; smem writable
        // ---- transform: w = e * inv; write W; scatter Af ----
#pragma unroll
        for (int i = 0; i < 8; i++) {
            int row = erow + i * 8;
            float inv = rsum[row];
            float4 w4;
            if (uniform) w4 = make_float4(U, U, U, U);
            else w4 = make_float4(e[i].x * inv, e[i].y * inv, e[i].z * inv, e[i].w * inv);
            *(float4*)&Wb[(size_t)row * SS + kt * 128 + ec0] = w4;
            Af[a_idx(row, ec0 + 0, 16)] = w4.x;
            Af[a_idx(row, ec0 + 1, 16)] = w4.y;
            Af[a_idx(row, ec0 + 2, 16)] = w4.z;
            Af[a_idx(row, ec0 + 3, 16)] = w4.w;
        }
        // ---- V tile (L2-resident) ----
#pragma unroll
        for (int i = 0; i < 8; i++) {
            int idx = t + i * 256;
            int kv = idx >> 4, d0 = (idx & 15) << 2;
            float4 vv = *(const float4*)&Vb[(size_t)(kt * 128 + kv) * DD + d0];
            Bf[b_idx(kv, d0 + 0, 16)] = vv.x;
            Bf[b_idx(kv, d0 + 1, 16)] = vv.y;
            Bf[b_idx(kv, d0 + 2, 16)] = vv.z;
            Bf[b_idx(kv, d0 + 3, 16)] = vv.w;
        }
        __syncthreads();

        // ---- prefetch next E tile (overlaps with MMA below) ----
        if (!uniform && kt + 1 < nkt) {
#pragma unroll
            for (int i = 0; i < 8; i++)
                e[i] = *(const float4*)&Wb[(size_t)(erow + i * 8) * SS + (kt + 1) * 128 + ec0];
        }

        // ---- MMA ----
#pragma unroll 4
        for (int s = 0; s < 16; s++) {
            float4 av = Af4[((wm * 16 + s) << 5) + lane];
            float4 ah, al;
            split4(av, ah, al);
#pragma unroll
            for (int nt = 0; nt < 4; nt++) {
                float2 bv = Bf2[(((wn * 4 + nt) * 16 + s) << 5) + lane];
                float2 bh, bl;
                split2(bv, bh, bl);
                mma8(acc[nt], ah, bh);
                mma8(acc[nt], al, bh);
                mma8(acc[nt], ah, bl);
            }
        }
    }

    // ---- tail zero-fill [kend, 2048) ----
    if (kend < SS) {
        const float4 z4 = make_float4(0.f, 0.f, 0.f, 0.f);
        const int c40 = (kend >> 2) + lane;
        for (int r = wid; r < 64; r += 8) {
            float4* Wr = (float4*)(Wb + (size_t)r * SS);
            for (int c4 = c40; c4 < SS / 4; c4 += 32) Wr[c4] = z4;
        }
    }

    // ---- epilogue ----
    const int g = lane >> 2, cp = (lane & 3) << 1;
    int row = qt * 64 + wm * 16 + g;
    float* Op0 = O + ((size_t)(b * SS + row)) * DD;
    float* Op1 = O + ((size_t)(b * SS + row + 8)) * DD;
#pragma unroll
    for (int nt = 0; nt < 4; nt++) {
        int col = wn * 32 + nt * 8 + cp;
        *(float2*)&Op0[col] = make_float2(acc[nt][0], acc[nt][1]);
        *(float2*)&Op1[col] = make_float2(acc[nt][2], acc[nt][3]);
    }
}

// ===================== fallback: normalize only (weights-only layout) =======
__global__ __launch_bounds__(256) void norm_only(float* __restrict__ W,
                                                 const int* __restrict__ vlen) {
    const int row = blockIdx.x, b = row >> 11;
    const int L = vlen[b];
    float* Wp = W + (size_t)row * SS;
    const int t = threadIdx.x;
    if (L == 0) {
        const float u = 1.0f / 2048.0f;
        for (int j = t * 4; j < SS; j += 1024) *(float4*)&Wp[j] = make_float4(u, u, u, u);
        return;
    }
    const float inv = 1.0f / g_rowsum[row];
    const int kend = ((L + 127) >> 7) << 7;
    for (int j = t * 4; j < SS; j += 1024) {
        float4 v = make_float4(0.f, 0.f, 0.f, 0.f);
        if (j < kend) {
            v = *(float4*)&Wp[j];
            v.x *= inv; v.y *= inv; v.z *= inv; v.w *= inv;
        }
        *(float4*)&Wp[j] = v;
    }
}

// ============================================================================
extern "C" void kernel_launch(void* const* d_in, const int* in_sizes, int n_in,
                              void* d_out, int out_size) {
    const float* Q = (const float*)d_in[0];
    const float* K = (const float*)d_in[1];
    const float* V = (const float*)d_in[2];
    const int* vlen = (const int*)d_in[3];

    const long long BSD = (long long)BB * SS * DD;
    const long long BSS = (long long)BB * SS * SS;

    float* out_o = nullptr;
    float* out_w;
    if ((long long)out_size >= BSD + BSS) {
        out_o = (float*)d_out;
        out_w = (float*)d_out + BSD;
    } else {
        out_w = (float*)d_out;
    }

    cudaFuncSetAttribute(qk_mma, cudaFuncAttributeMaxDynamicSharedMemorySize, QK_SMEM);
    cudaFuncSetAttribute(pv2, cudaFuncAttributeMaxDynamicSharedMemorySize, PV_SMEM);

    zero_rowsum<<<BB * SS / 1024, 256>>>();

    dim3 g1(SS / 128, SS / 128, BB);
    qk_mma<<<g1, 256, QK_SMEM>>>(Q, K, vlen, out_w);

    if (out_o) {
        dim3 g2(SS / 64, BB);
        pv2<<<g2, 256, PV_SMEM>>>(out_w, V, vlen, out_o);
    } else {
        norm_only<<<BB * SS, 256>>>(out_w, vlen);
    }
}

// round 17
// speedup vs baseline: 1.4817x; 1.3724x over previous
#include <cuda_runtime.h>
#include <cstdint>

#define BB 32
#define SS 2048
#define DD 64

__device__ float g_rowsum[BB * SS];  // per-(b,q-row) sum of exp over valid k

// ===================== tf32 split + mma.sync helpers ========================
__device__ __forceinline__ void split_tf32(float x, float& hi, float& lo) {
    uint32_t h;
    asm("cvt.rna.tf32.f32 %0, %1;" : "=r"(h) : "f"(x));
    hi = __uint_as_float(h);
    float rem = x - hi;
    uint32_t l;
    asm("cvt.rna.tf32.f32 %0, %1;" : "=r"(l) : "f"(rem));
    lo = __uint_as_float(l);
}
__device__ __forceinline__ void split4(float4 v, float4& h, float4& l) {
    split_tf32(v.x, h.x, l.x); split_tf32(v.y, h.y, l.y);
    split_tf32(v.z, h.z, l.z); split_tf32(v.w, h.w, l.w);
}
__device__ __forceinline__ void split2(float2 v, float2& h, float2& l) {
    split_tf32(v.x, h.x, l.x); split_tf32(v.y, h.y, l.y);
}

__device__ __forceinline__ void mma8(float* c, float4 a, float2 b) {
    asm volatile(
        "mma.sync.aligned.m16n8k8.row.col.f32.tf32.tf32.f32 "
        "{%0,%1,%2,%3}, {%4,%5,%6,%7}, {%8,%9}, {%0,%1,%2,%3};"
        : "+f"(c[0]), "+f"(c[1]), "+f"(c[2]), "+f"(c[3])
        : "r"(__float_as_uint(a.x)), "r"(__float_as_uint(a.y)),
          "r"(__float_as_uint(a.z)), "r"(__float_as_uint(a.w)),
          "r"(__float_as_uint(b.x)), "r"(__float_as_uint(b.y)));
}

// Padded fragment indices: slot stride 33 (lane-units) kills STS conflicts.
// A: slot = mt*KS + ks (staging varies ks within a row -> banks spread)
__device__ __forceinline__ int a_idx_p(int row, int col, int KS) {
    int mt = row >> 4, r = row & 15, ks = col >> 3, cc = col & 7;
    int lane = ((r & 7) << 2) | (cc & 3);
    int reg = (r >> 3) | ((cc >> 2) << 1);
    return (((mt * KS + ks) * 33 + lane) << 2) + reg;
}
// qk B: slot = nt*KS + ks (staging: fixed row -> fixed nt, ks varies)
__device__ __forceinline__ int b_idx_p(int kk, int n, int KS) {
    int nt = n >> 3, g = n & 7, ks = kk >> 3, c = kk & 7;
    int lane = (g << 2) | (c & 3);
    int reg = c >> 2;
    return (((nt * KS + ks) * 33 + lane) << 1) + reg;
}
// pv B: slot = ks*8 + nt (staging: fixed kv -> fixed ks, nt varies)
__device__ __forceinline__ int bp_idx(int kk, int n) {
    int nt = n >> 3, g = n & 7, ks = kk >> 3, c = kk & 7;
    int lane = (g << 2) | (c & 3);
    int reg = c >> 2;
    return (((ks * 8 + nt) * 33 + lane) << 1) + reg;
}

// ===================== K0: zero the rowsum scratch ==========================
__global__ void zero_rowsum() {
    int i = (blockIdx.x * 256 + threadIdx.x) * 4;
    *(float4*)&g_rowsum[i] = make_float4(0.f, 0.f, 0.f, 0.f);
}

// ===================== K1: E = exp((Q*0.125) @ K^T), + row sums =============
// A (=scaled Q, shared by 4 warps) pre-split into Afh/Afl smem; B split
// in-loop (2-warp redundancy only). Padded layouts.
// smem: Afh 33792 | Afl 33792 | Bf 33792 = 101376 (2 CTAs/SM)
#define QK_AFL 33792
#define QK_BF  67584
#define QK_SMEM 101376

__global__ __launch_bounds__(256, 2) void qk_mma(const float* __restrict__ Q,
                                                 const float* __restrict__ Km,
                                                 const int* __restrict__ vlen,
                                                 float* __restrict__ W) {
    const int kt = blockIdx.x, qt = blockIdx.y, b = blockIdx.z;
    const int L = vlen[b];
    if (L == 0 || kt * 128 >= L) return;

    extern __shared__ char S[];
    float* Afh = (float*)S;
    float* Afl = (float*)(S + QK_AFL);
    float* Bf  = (float*)(S + QK_BF);

    const int t = threadIdx.x;
    const float* Qb = Q + ((size_t)(b * SS + qt * 128)) * DD;
    const float* Kb = Km + ((size_t)(b * SS + kt * 128)) * DD;

#pragma unroll
    for (int i = 0; i < 8; i++) {
        int idx = t + i * 256;
        int row = idx >> 4, c0 = (idx & 15) << 2;
        float4 qv = *(const float4*)&Qb[row * DD + c0];
        float4 kv = *(const float4*)&Kb[row * DD + c0];
#pragma unroll
        for (int j = 0; j < 4; j++) {
            float hi, lo;
            split_tf32((&qv.x)[j] * 0.125f, hi, lo);
            int ia = a_idx_p(row, c0 + j, 8);
            Afh[ia] = hi; Afl[ia] = lo;
            Bf[b_idx_p(c0 + j, row, 8)] = (&kv.x)[j];
        }
    }
    __syncthreads();

    const int wid = t >> 5, lane = t & 31;
    const int wm = wid >> 2, wn = wid & 3;

    float acc[4][4][4];
#pragma unroll
    for (int mt = 0; mt < 4; mt++)
#pragma unroll
        for (int nt = 0; nt < 4; nt++)
#pragma unroll
            for (int r = 0; r < 4; r++) acc[mt][nt][r] = 0.0f;

    const float4* Afh4 = (const float4*)Afh;
    const float4* Afl4 = (const float4*)Afl;
    const float2* Bf2 = (const float2*)Bf;

#pragma unroll
    for (int s = 0; s < 8; s++) {
        float2 bh[4], bl[4];
#pragma unroll
        for (int nt = 0; nt < 4; nt++) {
            float2 bv = Bf2[(((wn * 4 + nt) * 8 + s)) * 33 + lane];
            split2(bv, bh[nt], bl[nt]);
        }
#pragma unroll
        for (int mt = 0; mt < 4; mt++) {
            int slot = ((wm * 4 + mt) * 8 + s) * 33 + lane;
            float4 ah = Afh4[slot];
            float4 al = Afl4[slot];
#pragma unroll
            for (int nt = 0; nt < 4; nt++) {
                mma8(acc[mt][nt], ah, bh[nt]);
                mma8(acc[mt][nt], al, bh[nt]);
                mma8(acc[mt][nt], ah, bl[nt]);
            }
        }
    }

    // ---- exp + mask + row-sum atomics (acc becomes E) ----
    const int g = lane >> 2, cp = (lane & 3) << 1;
    const int colbase = kt * 128 + wn * 32;
    float* rs = g_rowsum + (size_t)b * SS + qt * 128 + wm * 64;
#pragma unroll
    for (int mt = 0; mt < 4; mt++) {
        float s0 = 0.f, s1 = 0.f;
#pragma unroll
        for (int nt = 0; nt < 4; nt++) {
            int cg = colbase + nt * 8 + cp;
            float e0 = (cg < L) ? __expf(acc[mt][nt][0]) : 0.f;
            float e1 = (cg + 1 < L) ? __expf(acc[mt][nt][1]) : 0.f;
            float e2 = (cg < L) ? __expf(acc[mt][nt][2]) : 0.f;
            float e3 = (cg + 1 < L) ? __expf(acc[mt][nt][3]) : 0.f;
            acc[mt][nt][0] = e0; acc[mt][nt][1] = e1;
            acc[mt][nt][2] = e2; acc[mt][nt][3] = e3;
            s0 += e0 + e1; s1 += e2 + e3;
        }
        s0 += __shfl_xor_sync(0xffffffffu, s0, 1);
        s0 += __shfl_xor_sync(0xffffffffu, s0, 2);
        s1 += __shfl_xor_sync(0xffffffffu, s1, 1);
        s1 += __shfl_xor_sync(0xffffffffu, s1, 2);
        if ((lane & 3) == 0) {
            atomicAdd(&rs[mt * 16 + g], s0);
            atomicAdd(&rs[mt * 16 + g + 8], s1);
        }
    }
    __syncthreads();

    // ---- stage E -> coalesced store (Es reuses Afh/Afl space) ----
    float* Es = (float*)S;
#pragma unroll
    for (int mt = 0; mt < 4; mt++) {
        int row0 = wm * 64 + mt * 16 + g;
#pragma unroll
        for (int nt = 0; nt < 4; nt++) {
            int col0 = wn * 32 + nt * 8 + cp;
            *(float2*)&Es[row0 * 132 + col0] = make_float2(acc[mt][nt][0], acc[mt][nt][1]);
            *(float2*)&Es[(row0 + 8) * 132 + col0] = make_float2(acc[mt][nt][2], acc[mt][nt][3]);
        }
    }
    __syncthreads();

    float* Wp = W + ((size_t)(b * SS + qt * 128)) * SS + (size_t)kt * 128;
    const int c4 = t & 31;
    for (int rr = t >> 5; rr < 128; rr += 8)
        *(float4*)&Wp[(size_t)rr * SS + c4 * 4] = *(float4*)&Es[rr * 132 + c4 * 4];
}

// ===================== K2: single-pass normalize + O = W @ V ================
// B (=V, shared by 4 warps) pre-split into Bfh/Bfl; A (weights) split
// in-loop. E AND V register-prefetched one tile ahead (overlaps MMA).
// smem: Af 33792 | Bfh 33792 | Bfl 33792 | rsum 256 = 101632 (2 CTAs/SM)
#define PV_BFH 33792
#define PV_BFL 67584
#define PV_RS  101376
#define PV_SMEM 101632

__global__ __launch_bounds__(256, 2) void pv3(float* __restrict__ W,
                                              const float* __restrict__ V,
                                              const int* __restrict__ vlen,
                                              float* __restrict__ O) {
    const int qt = blockIdx.x, b = blockIdx.y;
    const int L = vlen[b];
    const bool uniform = (L == 0);
    const int nkt = uniform ? 16 : ((L + 127) >> 7);
    const int kend = nkt * 128;

    extern __shared__ char S[];
    float* Af  = (float*)S;              // 64x128 w (a_idx_p KS=16)
    float* Bfh = (float*)(S + PV_BFH);   // 128x64 V hi (bp_idx)
    float* Bfl = (float*)(S + PV_BFL);   // 128x64 V lo
    float* rsum = (float*)(S + PV_RS);

    const int t = threadIdx.x, wid = t >> 5, lane = t & 31;
    const int wm = wid >> 1, wn = wid & 1;

    float* Wb = W + ((size_t)(b * SS + qt * 64)) * SS;
    const float* Vb = V + (size_t)b * SS * DD;

    if (t < 64) {
        float s = uniform ? 1.0f : g_rowsum[(size_t)b * SS + qt * 64 + t];
        rsum[t] = 1.0f / s;
    }
    __syncthreads();

    float acc[4][4];
#pragma unroll
    for (int nt = 0; nt < 4; nt++)
#pragma unroll
        for (int r = 0; r < 4; r++) acc[nt][r] = 0.0f;

    const float4* Af4 = (const float4*)Af;
    const float2* Bfh2 = (const float2*)Bfh;
    const float2* Bfl2 = (const float2*)Bfl;
    const float U = 1.0f / 2048.0f;

    const int erow = t >> 5, ec0 = (t & 31) << 2;  // E slice: 8 rows/thread
    const int vkv = t >> 4, vd0 = (t & 15) << 2;   // V slice: 8 kv/thread
    float4 e[8], v[8];
    {
#pragma unroll
        for (int i = 0; i < 8; i++)
            v[i] = *(const float4*)&Vb[(size_t)(vkv + i * 16) * DD + vd0];
        if (!uniform)
#pragma unroll
            for (int i = 0; i < 8; i++)
                e[i] = *(const float4*)&Wb[(size_t)(erow + i * 8) * SS + ec0];
    }

    for (int kt = 0; kt < nkt; kt++) {
        __syncthreads();  // prev MMA reads done; smem writable
        // ---- transform E -> w; write W; scatter Af (fp32) ----
#pragma unroll
        for (int i = 0; i < 8; i++) {
            int row = erow + i * 8;
            float inv = rsum[row];
            float4 w4;
            if (uniform) w4 = make_float4(U, U, U, U);
            else w4 = make_float4(e[i].x * inv, e[i].y * inv, e[i].z * inv, e[i].w * inv);
            *(float4*)&Wb[(size_t)row * SS + kt * 128 + ec0] = w4;
            Af[a_idx_p(row, ec0 + 0, 16)] = w4.x;
            Af[a_idx_p(row, ec0 + 1, 16)] = w4.y;
            Af[a_idx_p(row, ec0 + 2, 16)] = w4.z;
            Af[a_idx_p(row, ec0 + 3, 16)] = w4.w;
        }
        // ---- V tile: split once, store hi/lo ----
#pragma unroll
        for (int i = 0; i < 8; i++) {
            int kv = vkv + i * 16;
#pragma unroll
            for (int j = 0; j < 4; j++) {
                float hi, lo;
                split_tf32((&v[i].x)[j], hi, lo);
                int ib = bp_idx(kv, vd0 + j);
                Bfh[ib] = hi; Bfl[ib] = lo;
            }
        }
        __syncthreads();

        // ---- prefetch next tile (overlaps MMA below) ----
        if (kt + 1 < nkt) {
#pragma unroll
            for (int i = 0; i < 8; i++)
                v[i] = *(const float4*)&Vb[(size_t)((kt + 1) * 128 + vkv + i * 16) * DD + vd0];
            if (!uniform)
#pragma unroll
                for (int i = 0; i < 8; i++)
                    e[i] = *(const float4*)&Wb[(size_t)(erow + i * 8) * SS + (kt + 1) * 128 + ec0];
        }

        // ---- MMA: 1 LDS128 + split4 + 8 LDS64 + 12 mma per step ----
#pragma unroll 4
        for (int s = 0; s < 16; s++) {
            float4 av = Af4[(wm * 16 + s) * 33 + lane];
            float4 ah, al;
            split4(av, ah, al);
#pragma unroll
            for (int nt = 0; nt < 4; nt++) {
                int slot = (s * 8 + wn * 4 + nt) * 33 + lane;
                float2 bh = Bfh2[slot];
                float2 bl = Bfl2[slot];
                mma8(acc[nt], ah, bh);
                mma8(acc[nt], al, bh);
                mma8(acc[nt], ah, bl);
            }
        }
    }

    // ---- tail zero-fill [kend, 2048) ----
    if (kend < SS) {
        const float4 z4 = make_float4(0.f, 0.f, 0.f, 0.f);
        const int c40 = (kend >> 2) + lane;
        for (int r = wid; r < 64; r += 8) {
            float4* Wr = (float4*)(Wb + (size_t)r * SS);
            for (int c4 = c40; c4 < SS / 4; c4 += 32) Wr[c4] = z4;
        }
    }

    // ---- epilogue ----
    const int g = lane >> 2, cp = (lane & 3) << 1;
    int row = qt * 64 + wm * 16 + g;
    float* Op0 = O + ((size_t)(b * SS + row)) * DD;
    float* Op1 = O + ((size_t)(b * SS + row + 8)) * DD;
#pragma unroll
    for (int nt = 0; nt < 4; nt++) {
        int col = wn * 32 + nt * 8 + cp;
        *(float2*)&Op0[col] = make_float2(acc[nt][0], acc[nt][1]);
        *(float2*)&Op1[col] = make_float2(acc[nt][2], acc[nt][3]);
    }
}

// ===================== fallback: normalize only (weights-only layout) =======
__global__ __launch_bounds__(256) void norm_only(float* __restrict__ W,
                                                 const int* __restrict__ vlen) {
    const int row = blockIdx.x, b = row >> 11;
    const int L = vlen[b];
    float* Wp = W + (size_t)row * SS;
    const int t = threadIdx.x;
    if (L == 0) {
        const float u = 1.0f / 2048.0f;
        for (int j = t * 4; j < SS; j += 1024) *(float4*)&Wp[j] = make_float4(u, u, u, u);
        return;
    }
    const float inv = 1.0f / g_rowsum[row];
    const int kend = ((L + 127) >> 7) << 7;
    for (int j = t * 4; j < SS; j += 1024) {
        float4 v = make_float4(0.f, 0.f, 0.f, 0.f);
        if (j < kend) {
            v = *(float4*)&Wp[j];
            v.x *= inv; v.y *= inv; v.z *= inv; v.w *= inv;
        }
        *(float4*)&Wp[j] = v;
    }
}

// ============================================================================
extern "C" void kernel_launch(void* const* d_in, const int* in_sizes, int n_in,
                              void* d_out, int out_size) {
    const float* Q = (const float*)d_in[0];
    const float* K = (const float*)d_in[1];
    const float* V = (const float*)d_in[2];
    const int* vlen = (const int*)d_in[3];

    const long long BSD = (long long)BB * SS * DD;
    const long long BSS = (long long)BB * SS * SS;

    float* out_o = nullptr;
    float* out_w;
    if ((long long)out_size >= BSD + BSS) {
        out_o = (float*)d_out;
        out_w = (float*)d_out + BSD;
    } else {
        out_w = (float*)d_out;
    }

    cudaFuncSetAttribute(qk_mma, cudaFuncAttributeMaxDynamicSharedMemorySize, QK_SMEM);
    cudaFuncSetAttribute(pv3, cudaFuncAttributeMaxDynamicSharedMemorySize, PV_SMEM);

    zero_rowsum<<<BB * SS / 1024, 256>>>();

    dim3 g1(SS / 128, SS / 128, BB);
    qk_mma<<<g1, 256, QK_SMEM>>>(Q, K, vlen, out_w);

    if (out_o) {
        dim3 g2(SS / 64, BB);
        pv3<<<g2, 256, PV_SMEM>>>(out_w, V, vlen, out_o);
    } else {
        norm_only<<<BB * SS, 256>>>(out_w, vlen);
    }
}